// round 1
// baseline (speedup 1.0000x reference)
#include <cuda_runtime.h>
#include <cuda_bf16.h>

// seg_loss: fused sigmoid-CE + boundary-edge loss + dice
// inputs: c_map float32 [16,4,512,512], gt int32 [16,4,512,512] (binary)
// output: scalar float32
//
// Scratch layout (doubles):
//   [0..63]    inter[bc]  = sum y*pred
//   [64..127]  ysum[bc]   = sum y
//   [128..191] psum[bc]   = sum pred
//   [192]      edge accumulator (sum over edge pixels of min(softplus(x),100))
//   [193]      ce accumulator   (sum of softplus(x) - x*y)
__device__ double g_acc[194];

#define NBC 64            // 16 batches * 4 classes
#define HW_W 512
#define HW_H 512
#define ROWS_PER_BLK 8
#define BLK_THREADS 256

__global__ void seg_init_kernel() {
    int t = threadIdx.x;
    if (t < 194) g_acc[t] = 0.0;
}

__device__ __forceinline__ float warp_red(float v) {
    v += __shfl_down_sync(0xffffffffu, v, 16);
    v += __shfl_down_sync(0xffffffffu, v, 8);
    v += __shfl_down_sync(0xffffffffu, v, 4);
    v += __shfl_down_sync(0xffffffffu, v, 2);
    v += __shfl_down_sync(0xffffffffu, v, 1);
    return v;
}

__global__ __launch_bounds__(BLK_THREADS)
void seg_main_kernel(const float* __restrict__ cmap, const int* __restrict__ gt) {
    // block -> (bc, 8-row band). 512/8 = 64 bands per image.
    int bc = blockIdx.x >> 6;
    int h0 = (blockIdx.x & 63) << 3;
    const size_t imgBase = (size_t)bc * (HW_W * HW_H);

    float inter = 0.f, ysum = 0.f, psum = 0.f, ce = 0.f, eg = 0.f;

    #pragma unroll
    for (int k = 0; k < 4; k++) {
        int g   = threadIdx.x + k * BLK_THREADS;   // 0..1023
        int row = g >> 7;                          // 0..7
        int xg  = g & 127;                         // int4-group within row
        int h   = h0 + row;
        size_t base = imgBase + (size_t)h * HW_W + (size_t)xg * 4;

        int4 cc = *(const int4*)(gt + base);
        int4 cu = (h > 0)          ? *(const int4*)(gt + base - HW_W) : make_int4(0,0,0,0);
        int4 cd = (h < HW_H - 1)   ? *(const int4*)(gt + base + HW_W) : make_int4(0,0,0,0);
        int lft = (xg > 0)   ? gt[base - 1] : 0;
        int rgt = (xg < 127) ? gt[base + 4] : 0;
        float4 xv = *(const float4*)(cmap + base);

        int   c[4]  = {cc.x, cc.y, cc.z, cc.w};
        int   u[4]  = {cu.x, cu.y, cu.z, cu.w};
        int   dn[4] = {cd.x, cd.y, cd.z, cd.w};
        float xs[4] = {xv.x, xv.y, xv.z, xv.w};

        #pragma unroll
        for (int i = 0; i < 4; i++) {
            int l = (i == 0) ? lft : c[i - 1];
            int r = (i == 3) ? rgt : c[i + 1];
            // binary morphology: dilation = OR, erosion = AND (zero-padded)
            int dila = c[i] | u[i] | dn[i] | l | r;
            int eros = c[i] & u[i] & dn[i] & l & r;
            int edge = dila & (eros ^ 1);

            float x = xs[i];
            float e  = __expf(-fabsf(x));                     // exp(-|x|) in (0,1]
            float sp = fmaxf(x, 0.0f) + __logf(1.0f + e);     // softplus(x)
            float inv = __fdividef(1.0f, 1.0f + e);
            float pred = (x >= 0.0f) ? inv : e * inv;         // sigmoid(x)

            float y = (float)c[i];
            ysum  += y;
            psum  += pred;
            inter += y * pred;
            ce    += sp - x * y;
            // edge term: -max(log1p(-pred),-100) = min(softplus(x),100) on edge px
            if (edge) eg += fminf(sp, 100.0f);
        }
    }

    // block reduction of 5 scalars
    inter = warp_red(inter);
    ysum  = warp_red(ysum);
    psum  = warp_red(psum);
    ce    = warp_red(ce);
    eg    = warp_red(eg);

    __shared__ float sred[8][5];
    int lane = threadIdx.x & 31;
    int wid  = threadIdx.x >> 5;
    if (lane == 0) {
        sred[wid][0] = inter; sred[wid][1] = ysum; sred[wid][2] = psum;
        sred[wid][3] = ce;    sred[wid][4] = eg;
    }
    __syncthreads();
    if (wid == 0) {
        float v0 = (lane < 8) ? sred[lane][0] : 0.f;
        float v1 = (lane < 8) ? sred[lane][1] : 0.f;
        float v2 = (lane < 8) ? sred[lane][2] : 0.f;
        float v3 = (lane < 8) ? sred[lane][3] : 0.f;
        float v4 = (lane < 8) ? sred[lane][4] : 0.f;
        v0 = warp_red(v0); v1 = warp_red(v1); v2 = warp_red(v2);
        v3 = warp_red(v3); v4 = warp_red(v4);
        if (lane == 0) {
            atomicAdd(&g_acc[bc],        (double)v0);
            atomicAdd(&g_acc[64 + bc],   (double)v1);
            atomicAdd(&g_acc[128 + bc],  (double)v2);
            atomicAdd(&g_acc[193],       (double)v3);
            atomicAdd(&g_acc[192],       (double)v4);
        }
    }
}

__global__ void seg_final_kernel(float* __restrict__ out) {
    const double SMOOTH = 0.0001;
    double dice = 0.0;
    #pragma unroll
    for (int bc = 0; bc < NBC; bc++) {
        double sc = (2.0 * g_acc[bc] + SMOOTH)
                  / (g_acc[64 + bc] + g_acc[128 + bc] + SMOOTH);
        dice += (1.0 - sc);
    }
    dice *= (1.0 / 16.0);  // mean over batch, sum over classes
    const double N = 16.0 * 4.0 * 512.0 * 512.0;
    double edge_l = g_acc[192] / N;
    double ce_l   = g_acc[193] / N;
    out[0] = (float)(ce_l + edge_l + dice);
}

extern "C" void kernel_launch(void* const* d_in, const int* in_sizes, int n_in,
                              void* d_out, int out_size) {
    const float* cmap = (const float*)d_in[0];
    const int*   gt   = (const int*)d_in[1];
    float* out = (float*)d_out;

    seg_init_kernel<<<1, 256>>>();
    // 16*4 images * 64 bands = 4096 blocks
    seg_main_kernel<<<4096, BLK_THREADS>>>(cmap, gt);
    seg_final_kernel<<<1, 1>>>(out);
}

// round 4
// speedup vs baseline: 1.2997x; 1.2997x over previous
#include <cuda_runtime.h>
#include <cuda_bf16.h>

// seg_loss: fused sigmoid-CE + boundary-edge loss + dice
// inputs: c_map float32 [16,4,512,512], gt int32 [16,4,512,512] (binary)
// output: scalar float32
//
// No-init design: 2048 blocks each write 5 float partials to their own slot;
// finalize kernel reduces. No atomics, no zeroing kernel.

#define HW_W 512
#define HW_H 512
#define ROWS 16           // rows per block band
#define BANDS 32          // 512 / 16 bands per image
#define NBC 64            // 16 batches * 4 classes
#define NBLK 2048         // NBC * BANDS
#define TPB 128           // one int4-group per thread across a row

__device__ float g_inter[NBLK];
__device__ float g_ysum[NBLK];
__device__ float g_psum[NBLK];
__device__ float g_ce[NBLK];
__device__ float g_eg[NBLK];

__device__ __forceinline__ float warp_redf(float v) {
    v += __shfl_down_sync(0xffffffffu, v, 16);
    v += __shfl_down_sync(0xffffffffu, v, 8);
    v += __shfl_down_sync(0xffffffffu, v, 4);
    v += __shfl_down_sync(0xffffffffu, v, 2);
    v += __shfl_down_sync(0xffffffffu, v, 1);
    return v;
}
__device__ __forceinline__ double warp_redd(double v) {
    v += __shfl_down_sync(0xffffffffu, v, 16);
    v += __shfl_down_sync(0xffffffffu, v, 8);
    v += __shfl_down_sync(0xffffffffu, v, 4);
    v += __shfl_down_sync(0xffffffffu, v, 2);
    v += __shfl_down_sync(0xffffffffu, v, 1);
    return v;
}

__global__ __launch_bounds__(TPB)
void seg_main_kernel(const float* __restrict__ cmap, const int* __restrict__ gt) {
    const int bc   = blockIdx.x >> 5;          // image (b,c)
    const int band = blockIdx.x & 31;
    const int h0   = band * ROWS;
    const int xg   = threadIdx.x;              // int4-group column 0..127
    const int lane = threadIdx.x & 31;

    const size_t img = (size_t)bc * (HW_W * HW_H);
    const size_t colBase = img + (size_t)xg * 4;

    float inter = 0.f, ysum = 0.f, psum = 0.f, ce = 0.f, eg = 0.f;

    // rolling rows: prev (up), cur, nxt (down)
    int4 prev = (h0 > 0) ? *(const int4*)(gt + colBase + (size_t)(h0 - 1) * HW_W)
                         : make_int4(0, 0, 0, 0);
    int4 cur  = *(const int4*)(gt + colBase + (size_t)h0 * HW_W);

    #pragma unroll
    for (int r = 0; r < ROWS; r++) {
        const int h = h0 + r;
        const size_t rowBase = colBase + (size_t)h * HW_W;

        int4 nxt = (h < HW_H - 1) ? *(const int4*)(gt + rowBase + HW_W)
                                  : make_int4(0, 0, 0, 0);
        float4 xv = *(const float4*)(cmap + rowBase);

        // horizontal neighbors of this thread's 4-pixel group
        int lft = __shfl_up_sync(0xffffffffu, cur.w, 1);
        int rgt = __shfl_down_sync(0xffffffffu, cur.x, 1);
        if (lane == 0)  lft = (xg > 0)   ? gt[rowBase - 1] : 0;   // cross-warp / img edge
        if (lane == 31) rgt = (xg < 127) ? gt[rowBase + 4] : 0;

        int c[4]  = {cur.x, cur.y, cur.z, cur.w};
        int u[4]  = {prev.x, prev.y, prev.z, prev.w};
        int dn[4] = {nxt.x, nxt.y, nxt.z, nxt.w};
        float xs[4] = {xv.x, xv.y, xv.z, xv.w};

        #pragma unroll
        for (int i = 0; i < 4; i++) {
            int l = (i == 0) ? lft : c[i - 1];
            int rr = (i == 3) ? rgt : c[i + 1];
            int dila = c[i] | u[i] | dn[i] | l | rr;
            int eros = c[i] & u[i] & dn[i] & l & rr;
            int edge = dila & (eros ^ 1);

            float x = xs[i];
            float e   = __expf(-fabsf(x));                   // exp(-|x|)
            float sp  = fmaxf(x, 0.0f) + __logf(1.0f + e);   // softplus(x)
            float inv = __fdividef(1.0f, 1.0f + e);
            float pred = (x >= 0.0f) ? inv : e * inv;        // sigmoid(x)

            float y = (float)c[i];
            ysum  += y;
            psum  += pred;
            inter += y * pred;
            ce    += sp - x * y;
            if (edge) eg += fminf(sp, 100.0f);               // -max(log1p(-pe),-100)
        }

        prev = cur; cur = nxt;
    }

    // block reduction (4 warps)
    inter = warp_redf(inter);
    ysum  = warp_redf(ysum);
    psum  = warp_redf(psum);
    ce    = warp_redf(ce);
    eg    = warp_redf(eg);

    __shared__ float sred[4][5];
    int wid = threadIdx.x >> 5;
    if (lane == 0) {
        sred[wid][0] = inter; sred[wid][1] = ysum; sred[wid][2] = psum;
        sred[wid][3] = ce;    sred[wid][4] = eg;
    }
    __syncthreads();
    if (threadIdx.x == 0) {
        float v0 = 0.f, v1 = 0.f, v2 = 0.f, v3 = 0.f, v4 = 0.f;
        #pragma unroll
        for (int w = 0; w < 4; w++) {
            v0 += sred[w][0]; v1 += sred[w][1]; v2 += sred[w][2];
            v3 += sred[w][3]; v4 += sred[w][4];
        }
        g_inter[blockIdx.x] = v0;
        g_ysum[blockIdx.x]  = v1;
        g_psum[blockIdx.x]  = v2;
        g_ce[blockIdx.x]    = v3;
        g_eg[blockIdx.x]    = v4;
    }
}

__global__ __launch_bounds__(256)
void seg_final_kernel(float* __restrict__ out) {
    const double SMOOTH = 0.0001;
    const int t = threadIdx.x;

    // dice: threads 0..63 handle one (b,c) each — parallel fp64 division
    double dice = 0.0;
    if (t < NBC) {
        double I = 0.0, Y = 0.0, P = 0.0;
        #pragma unroll 8
        for (int b = 0; b < BANDS; b++) {
            int s = t * BANDS + b;
            I += (double)g_inter[s];
            Y += (double)g_ysum[s];
            P += (double)g_psum[s];
        }
        dice = 1.0 - (2.0 * I + SMOOTH) / (Y + P + SMOOTH);
    }

    // ce / edge: all 256 threads stride over 2048 slots
    double ce = 0.0, eg = 0.0;
    for (int s = t; s < NBLK; s += 256) {
        ce += (double)g_ce[s];
        eg += (double)g_eg[s];
    }

    dice = warp_redd(dice);
    ce   = warp_redd(ce);
    eg   = warp_redd(eg);

    __shared__ double sd[8][3];
    int lane = t & 31, wid = t >> 5;
    if (lane == 0) { sd[wid][0] = dice; sd[wid][1] = ce; sd[wid][2] = eg; }
    __syncthreads();
    if (t == 0) {
        double D = 0.0, C = 0.0, E = 0.0;
        #pragma unroll
        for (int w = 0; w < 8; w++) { D += sd[w][0]; C += sd[w][1]; E += sd[w][2]; }
        const double N = 16.0 * 4.0 * 512.0 * 512.0;
        out[0] = (float)(C / N + E / N + D / 16.0);
    }
}

extern "C" void kernel_launch(void* const* d_in, const int* in_sizes, int n_in,
                              void* d_out, int out_size) {
    const float* cmap = (const float*)d_in[0];
    const int*   gt   = (const int*)d_in[1];
    float* out = (float*)d_out;

    seg_main_kernel<<<NBLK, TPB>>>(cmap, gt);
    seg_final_kernel<<<1, 256>>>(out);
}